// round 11
// baseline (speedup 1.0000x reference)
#include <cuda_runtime.h>

#define NSLOPE 0.2f
#define NMAX   50048
#define EMAX   655360

// ---- device scratch (no runtime allocation allowed) ----
__device__ float g_h[NMAX * 128];     // h = in @ W
__device__ float g_y[NMAX * 128];     // layer output (input to next layer)
__device__ float g_o2[NMAX * 64];     // final pre-log-softmax
__device__ float g_as[NMAX];          // h . a_src per node
__device__ float g_ad[NMAX];          // h . a_dst per node
__device__ int   g_deg[NMAX];         // in-degree (w/o self loop)
__device__ int   g_start[NMAX];       // CSR segment start (by dst)
__device__ int   g_cur[NMAX];         // scatter cursors
__device__ int   g_csr[EMAX];         // src node per CSR slot
__device__ int   g_cnt;               // global slot allocator

// ========================== CSR build (4 kernels) ==========================

__global__ void k_zero(int n) {
    int i = blockIdx.x * 256 + threadIdx.x;
    if (i < n) g_deg[i] = 0;
    if (i == 0) g_cnt = 0;
}

// 4 independent chains per thread for MLP against ATOMG latency
__global__ void k_count(const int* __restrict__ dst, int e, int T) {
    int i = blockIdx.x * 256 + threadIdx.x;
#pragma unroll
    for (int t = 0; t < 4; t++) {
        int j = i + t * T;
        if (j < e) atomicAdd(&g_deg[dst[j]], 1);
    }
}

// block-aggregated segment allocation + self-loop planting
__global__ void k_alloc(int n) {
    __shared__ int s[256];
    __shared__ int base;
    int tid = threadIdx.x;
    int i = blockIdx.x * 256 + tid;
    int deg = (i < n) ? g_deg[i] + 1 : 0;  // +1 self loop
    s[tid] = deg;
    __syncthreads();
    for (int off = 1; off < 256; off <<= 1) {
        int a = s[tid];
        int b = (tid >= off) ? s[tid - off] : 0;
        __syncthreads();
        s[tid] = a + b;
        __syncthreads();
    }
    if (tid == 255) base = atomicAdd(&g_cnt, s[255]);
    __syncthreads();
    if (i < n) {
        int st = base + s[tid] - deg;
        g_start[i] = st;
        g_csr[st] = i;   // self-loop occupies slot 0
        g_cur[i] = 1;
    }
}

__global__ void k_scatter(const int* __restrict__ src, const int* __restrict__ dst,
                          int e, int T) {
    int i = blockIdx.x * 256 + threadIdx.x;
#pragma unroll
    for (int t = 0; t < 4; t++) {
        int j = i + t * T;
        if (j < e) {
            int d = dst[j];
            int p = atomicAdd(&g_cur[d], 1);
            g_csr[g_start[d] + p] = src[j];
        }
    }
}

// ============== GEMM (scalar FFMA, 8x8 blocking) + fused attention dots ==============
// A: [M,128] row-major, W: [128,BN] row-major, H: [M,BN]
// Block 256 threads, tile 128 x BN, BK=16. A-tile stored k-major (transposed)
// so per-thread row fragments load as conflict-free LDS.128.

template <int BN>
__global__ __launch_bounds__(256) void k_gemm(
    const float* __restrict__ A, const float* __restrict__ W,
    float* __restrict__ H, const float* __restrict__ a_s,
    const float* __restrict__ a_d, int M)
{
    constexpr int TXc = BN / 8;      // col groups (16 or 8), 8 cols each
    constexpr int TYr = 256 / TXc;   // row groups (16 or 32)
    constexpr int RPT = 128 / TYr;   // rows per thread (8 or 4)
    __shared__ float Xs[16][128];    // [k][row]  (transposed A tile)
    __shared__ float Ws[16][BN];     // [k][col]

    int tid = threadIdx.x;
    int tx = tid % TXc, ty = tid / TXc;
    int lane = tid & 31;
    int row0 = blockIdx.x * 128;
    int r0 = ty * RPT;
    int c0 = tx * 8;

    float acc[RPT][8];
#pragma unroll
    for (int j = 0; j < RPT; j++)
#pragma unroll
        for (int c = 0; c < 8; c++) acc[j][c] = 0.f;

    for (int k0 = 0; k0 < 128; k0 += 16) {
        // A tile: 128 rows x 16 k = 512 float4 reads, transpose-store to Xs[k][row]
#pragma unroll
        for (int t = 0; t < 2; t++) {
            int i = tid + t * 256;
            int r = i >> 2, kc = (i & 3) * 4;
            int gr = row0 + r;
            float4 v = make_float4(0.f, 0.f, 0.f, 0.f);
            if (gr < M) v = *(const float4*)(A + (size_t)gr * 128 + k0 + kc);
            Xs[kc + 0][r] = v.x;
            Xs[kc + 1][r] = v.y;
            Xs[kc + 2][r] = v.z;
            Xs[kc + 3][r] = v.w;
        }
        // W tile: 16 x BN
#pragma unroll
        for (int t = 0; t < BN / 64; t++) {
            int i = tid + t * 256;
            int kr = i / (BN / 4), c4 = (i % (BN / 4)) * 4;
            *(float4*)&Ws[kr][c4] = *(const float4*)(W + (size_t)(k0 + kr) * BN + c4);
        }
        __syncthreads();
#pragma unroll
        for (int kk = 0; kk < 16; kk++) {
            float a[RPT];
            *(float4*)&a[0] = *(const float4*)&Xs[kk][r0];
            if (RPT == 8) *(float4*)&a[4] = *(const float4*)&Xs[kk][r0 + 4];
            float w[8];
            *(float4*)&w[0] = *(const float4*)&Ws[kk][c0];
            *(float4*)&w[4] = *(const float4*)&Ws[kk][c0 + 4];
#pragma unroll
            for (int j = 0; j < RPT; j++)
#pragma unroll
                for (int c = 0; c < 8; c++) acc[j][c] += a[j] * w[c];
        }
        __syncthreads();
    }

    float asv[8], adv[8];
#pragma unroll
    for (int c = 0; c < 8; c++) {
        asv[c] = a_s[c0 + c];
        adv[c] = a_d[c0 + c];
    }

#pragma unroll
    for (int j = 0; j < RPT; j++) {
        int r = row0 + r0 + j;
        if (r < M) {
            *(float4*)(H + (size_t)r * BN + c0)     =
                make_float4(acc[j][0], acc[j][1], acc[j][2], acc[j][3]);
            *(float4*)(H + (size_t)r * BN + c0 + 4) =
                make_float4(acc[j][4], acc[j][5], acc[j][6], acc[j][7]);
        }
        float sa = 0.f, sd = 0.f;
#pragma unroll
        for (int c = 0; c < 8; c++) {
            sa += acc[j][c] * asv[c];
            sd += acc[j][c] * adv[c];
        }
#pragma unroll
        for (int off = TXc / 2; off; off >>= 1) {
            sa += __shfl_xor_sync(0xffffffffu, sa, off);
            sd += __shfl_xor_sync(0xffffffffu, sd, off);
        }
        if ((lane & (TXc - 1)) == 0 && r < M) {
            g_as[r] = sa;
            g_ad[r] = sd;
        }
    }
}

// ============ warp-per-dst-node segment softmax + weighted gather ============

template <int D, bool SILU>
__global__ void k_agg(const float* __restrict__ h, const float* __restrict__ bias,
                      float* __restrict__ out, int n) {
    constexpr int MAXDEG = 128;
    constexpr int FP = D / 32;  // floats per lane (4 or 2)
    __shared__ float wsh[8][MAXDEG];
    __shared__ int ssh[8][MAXDEG];
    int warp = threadIdx.x >> 5, lane = threadIdx.x & 31;
    int d = blockIdx.x * 8 + warp;
    if (d >= n) return;
    int st = g_start[d];
    int deg = g_deg[d] + 1;
    float ad = g_ad[d];
    int f = lane * FP;
    float acc[FP];
#pragma unroll
    for (int j = 0; j < FP; j++) acc[j] = 0.f;
    float inv;

    if (deg <= MAXDEG) {
        float m = -1e30f;
        for (int i = lane; i < deg; i += 32) {
            int s = g_csr[st + i];
            ssh[warp][i] = s;
            float al = g_as[s] + ad;
            al = al > 0.f ? al : NSLOPE * al;
            wsh[warp][i] = al;
            m = fmaxf(m, al);
        }
#pragma unroll
        for (int o = 16; o; o >>= 1) m = fmaxf(m, __shfl_xor_sync(0xffffffffu, m, o));
        __syncwarp();
        float den = 0.f;
        for (int i = lane; i < deg; i += 32) {
            float w = __expf(wsh[warp][i] - m);
            wsh[warp][i] = w;
            den += w;
        }
#pragma unroll
        for (int o = 16; o; o >>= 1) den += __shfl_xor_sync(0xffffffffu, den, o);
        __syncwarp();
        inv = 1.f / den;
        // phase 2: warp gathers neighbor h rows, 4x unrolled for L2 MLP
        int i = 0;
        for (; i + 4 <= deg; i += 4) {
#pragma unroll
            for (int u = 0; u < 4; u++) {
                int s = ssh[warp][i + u];
                float c = wsh[warp][i + u];
                const float* hp = h + (size_t)s * D + f;
                if constexpr (FP == 4) {
                    float4 v = *(const float4*)hp;
                    acc[0] += c * v.x;
                    acc[1] += c * v.y;
                    acc[2] += c * v.z;
                    acc[3] += c * v.w;
                } else {
                    float2 v = *(const float2*)hp;
                    acc[0] += c * v.x;
                    acc[1] += c * v.y;
                }
            }
        }
        for (; i < deg; i++) {
            int s = ssh[warp][i];
            float c = wsh[warp][i];
            const float* hp = h + (size_t)s * D + f;
            if constexpr (FP == 4) {
                float4 v = *(const float4*)hp;
                acc[0] += c * v.x;
                acc[1] += c * v.y;
                acc[2] += c * v.z;
                acc[3] += c * v.w;
            } else {
                float2 v = *(const float2*)hp;
                acc[0] += c * v.x;
                acc[1] += c * v.y;
            }
        }
    } else {
        // fallback: online softmax (never expected at these degrees)
        float m = -1e30f, den = 0.f;
        for (int i = 0; i < deg; i++) {
            int s = g_csr[st + i];
            float al = g_as[s] + ad;
            al = al > 0.f ? al : NSLOPE * al;
            float nm = fmaxf(m, al);
            float sc = __expf(m - nm);
            float w = __expf(al - nm);
            den = den * sc + w;
            const float* hp = h + (size_t)s * D + f;
#pragma unroll
            for (int j = 0; j < FP; j++) acc[j] = acc[j] * sc + w * hp[j];
            m = nm;
        }
        inv = 1.f / den;
    }

#pragma unroll
    for (int j = 0; j < FP; j++) {
        float v = acc[j] * inv + bias[f + j];
        if (SILU) v = v / (1.f + __expf(-v));
        out[(size_t)d * D + f + j] = v;
    }
}

// ========================== log_softmax over 64 cols ==========================

__global__ void k_lsm(const float* __restrict__ in, float* __restrict__ out, int n) {
    int warp = threadIdx.x >> 5, lane = threadIdx.x & 31;
    int r = blockIdx.x * 8 + warp;
    if (r >= n) return;
    float2 v = *(const float2*)&in[(size_t)r * 64 + lane * 2];
    float m = fmaxf(v.x, v.y);
#pragma unroll
    for (int o = 16; o; o >>= 1) m = fmaxf(m, __shfl_xor_sync(0xffffffffu, m, o));
    float s = __expf(v.x - m) + __expf(v.y - m);
#pragma unroll
    for (int o = 16; o; o >>= 1) s += __shfl_xor_sync(0xffffffffu, s, o);
    float l = m + __logf(s);
    float2 o2 = make_float2(v.x - l, v.y - l);
    *(float2*)&out[(size_t)r * 64 + lane * 2] = o2;
}

// ========================== host launcher ==========================

extern "C" void kernel_launch(void* const* d_in, const int* in_sizes, int n_in,
                              void* d_out, int out_size) {
    const float* x   = (const float*)d_in[0];
    const int*   ei  = (const int*)d_in[1];
    const float* W0  = (const float*)d_in[2];
    const float* as0 = (const float*)d_in[3];
    const float* ad0 = (const float*)d_in[4];
    const float* b0  = (const float*)d_in[5];
    const float* W1  = (const float*)d_in[6];
    const float* as1 = (const float*)d_in[7];
    const float* ad1 = (const float*)d_in[8];
    const float* b1  = (const float*)d_in[9];
    const float* W2  = (const float*)d_in[10];
    const float* as2 = (const float*)d_in[11];
    const float* ad2 = (const float*)d_in[12];
    const float* b2  = (const float*)d_in[13];

    int n = in_sizes[0] / 128;  // 50000
    int e = in_sizes[1] / 2;    // 600000
    const int* src = ei;
    const int* dst = ei + e;
    float* outp = (float*)d_out;

    float *ph, *py, *po2;
    cudaGetSymbolAddress((void**)&ph, g_h);
    cudaGetSymbolAddress((void**)&py, g_y);
    cudaGetSymbolAddress((void**)&po2, g_o2);

    int nbN = (n + 255) / 256;
    int nbE4 = (e + 1023) / 1024;
    int T = nbE4 * 256;
    int nbG = (n + 127) / 128;
    int nbA = (n + 7) / 8;
    int nbW = (n + 7) / 8;

    // CSR by dst (includes self-loops at segment head)
    k_zero<<<nbN, 256>>>(n);
    k_count<<<nbE4, 256>>>(dst, e, T);
    k_alloc<<<nbN, 256>>>(n);
    k_scatter<<<nbE4, 256>>>(src, dst, e, T);

    // layer 0: 128 -> 128, SiLU
    k_gemm<128><<<nbG, 256>>>(x, W0, ph, as0, ad0, n);
    k_agg<128, true><<<nbA, 256>>>(ph, b0, py, n);

    // layer 1: 128 -> 128, SiLU
    k_gemm<128><<<nbG, 256>>>(py, W1, ph, as1, ad1, n);
    k_agg<128, true><<<nbA, 256>>>(ph, b1, py, n);

    // layer 2: 128 -> 64, no SiLU, then log_softmax
    k_gemm<64><<<nbG, 256>>>(py, W2, ph, as2, ad2, n);
    k_agg<64, false><<<nbA, 256>>>(ph, b2, po2, n);
    k_lsm<<<nbW, 256>>>(po2, outp, n);
}